// round 13
// baseline (speedup 1.0000x reference)
#include <cuda_runtime.h>
#include <cuda_bf16.h>

// out[k][d] = mult_k * sum_i W_k[eb_input[i]][d]   (offsets mathematically dead).
//
// Split-range pipeline:
//   histA: RED rows < split          (normal launch)
//   histB: RED rows >= split, 592 blocks (half SM capacity), PDL trigger at entry
//   sweepA: rows [0,split)  -- PDL secondary, NO dependency sync (histA already
//           complete when histB starts); overlaps histB (op-bound vs data-bound)
//   sweepB: rows [split,2M) -- normal launch (waits histB + sweepA)
//   final : separate tiny kernel (fusions measured slower)

#define MAX_EMB 2000000

__device__ unsigned int g_count[MAX_EMB];   // zero at load; sweeps re-zero
__device__ double g_acc[9 * 64];            // padded accumulators

// ---------------------------------------------------------------------------
// histA: one int4/thread (best measured form), RED only idx < split.
// ---------------------------------------------------------------------------
__global__ void k_histA(const int* __restrict__ idx, int n_idx, int split) {
    int t = blockIdx.x * blockDim.x + threadIdx.x;
    int n4 = n_idx >> 2;
    if (t < n4) {
        int4 a = __ldcs((const int4*)idx + t);
        if (a.x < split) atomicAdd(&g_count[a.x], 1u);
        if (a.y < split) atomicAdd(&g_count[a.y], 1u);
        if (a.z < split) atomicAdd(&g_count[a.z], 1u);
        if (a.w < split) atomicAdd(&g_count[a.w], 1u);
    }
    if (blockIdx.x == 0) {
        int rem = n_idx & 3;
        if ((int)threadIdx.x < rem) {
            int r = idx[(n4 << 2) + threadIdx.x];
            if (r < split) atomicAdd(&g_count[r], 1u);
        }
    }
}

// ---------------------------------------------------------------------------
// histB: grid-stride (592 blocks = half SM capacity), RED only idx >= split.
// Triggers PDL completion at entry so sweepA can co-reside immediately.
// ---------------------------------------------------------------------------
__global__ void k_histB(const int* __restrict__ idx, int n_idx, int split) {
    cudaTriggerProgrammaticLaunchCompletion();
    int T = gridDim.x * blockDim.x;
    int n4 = n_idx >> 2;
    for (int t = blockIdx.x * blockDim.x + threadIdx.x; t < n4; t += T) {
        int4 a = __ldcs((const int4*)idx + t);
        if (a.x >= split) atomicAdd(&g_count[a.x], 1u);
        if (a.y >= split) atomicAdd(&g_count[a.y], 1u);
        if (a.z >= split) atomicAdd(&g_count[a.z], 1u);
        if (a.w >= split) atomicAdd(&g_count[a.w], 1u);
    }
    if (blockIdx.x == 0) {
        int rem = n_idx & 3;
        if ((int)threadIdx.x < rem) {
            int r = idx[(n4 << 2) + threadIdx.x];
            if (r >= split) atomicAdd(&g_count[r], 1u);
        }
    }
}

// ---------------------------------------------------------------------------
// sweep over row range [row_lo, row_hi): R1 hot loop (measured 10.4us full).
// row_lo must be a multiple of 4.
// ---------------------------------------------------------------------------
__global__ void k_sweep(const float* __restrict__ W0,
                        const float* __restrict__ W1,
                        const float* __restrict__ W2,
                        int row_lo, int row_hi) {
    int t = blockIdx.x * blockDim.x + threadIdx.x;
    int r0 = row_lo + t * 4;

    float acc[9];
#pragma unroll
    for (int k = 0; k < 9; k++) acc[k] = 0.0f;

    if (r0 + 4 <= row_hi) {
        uint4 c4 = *(const uint4*)&g_count[r0];
        *(uint4*)&g_count[r0] = make_uint4(0u, 0u, 0u, 0u);   // re-init for replay
        float c0 = (float)c4.x, c1 = (float)c4.y, c2 = (float)c4.z, c3 = (float)c4.w;

        const float* Ws[3] = {W0, W1, W2};
        int q = r0 >> 2;                                       // = 3*t base / 3
#pragma unroll
        for (int k = 0; k < 3; k++) {
            const float4* Wv = (const float4*)Ws[k] + 3 * q;   // 12 floats = 4 rows
            float4 a = __ldg(Wv + 0);
            float4 b = __ldg(Wv + 1);
            float4 d = __ldg(Wv + 2);
            // rows: r0: a.x a.y a.z | r0+1: a.w b.x b.y | r0+2: b.z b.w d.x | r0+3: d.y d.z d.w
            acc[3 * k + 0] += c0 * a.x + c1 * a.w + c2 * b.z + c3 * d.y;
            acc[3 * k + 1] += c0 * a.y + c1 * b.x + c2 * b.w + c3 * d.z;
            acc[3 * k + 2] += c0 * a.z + c1 * b.y + c2 * d.x + c3 * d.w;
        }
    } else if (r0 < row_hi) {
        for (int r = r0; r < row_hi; r++) {
            float c = (float)g_count[r];
            g_count[r] = 0u;
            const float* Ws[3] = {W0, W1, W2};
#pragma unroll
            for (int k = 0; k < 3; k++) {
                acc[3 * k + 0] += c * Ws[k][3 * r + 0];
                acc[3 * k + 1] += c * Ws[k][3 * r + 1];
                acc[3 * k + 2] += c * Ws[k][3 * r + 2];
            }
        }
    }

    unsigned lane = threadIdx.x & 31u;
    unsigned warp = threadIdx.x >> 5;
#pragma unroll
    for (int k = 0; k < 9; k++) {
#pragma unroll
        for (int o = 16; o > 0; o >>= 1)
            acc[k] += __shfl_down_sync(0xffffffffu, acc[k], o);
    }

    __shared__ float s_red[8][9];
    if (lane == 0) {
#pragma unroll
        for (int k = 0; k < 9; k++) s_red[warp][k] = acc[k];
    }
    __syncthreads();

    if (threadIdx.x < 9) {
        double s = 0.0;
#pragma unroll
        for (int w = 0; w < 8; w++) s += (double)s_red[w][threadIdx.x];
        atomicAdd(&g_acc[threadIdx.x * 64], s);
    }
}

// ---------------------------------------------------------------------------
__global__ void k_final(float* __restrict__ out) {
    int i = threadIdx.x;
    if (i < 9) {
        const float mult[3] = {5.0f, 10.0f, 6.0f};
        double v = g_acc[i * 64];
        g_acc[i * 64] = 0.0;
        out[i] = (float)((double)mult[i / 3] * v);
    }
}

// ---------------------------------------------------------------------------
extern "C" void kernel_launch(void* const* d_in, const int* in_sizes, int n_in,
                              void* d_out, int out_size) {
    const int*   idx = (const int*)d_in[0];
    // d_in[1] = eb_offset : mathematically unused
    const float* W0  = (const float*)d_in[2];
    const float* W1  = (const float*)d_in[3];
    const float* W2  = (const float*)d_in[4];
    int n_idx   = in_sizes[0];
    int num_emb = in_sizes[2] / 3;
    int split   = (num_emb / 2) & ~3;        // multiple of 4

    int n4 = n_idx >> 2;
    int histA_blocks = (n4 + 255) / 256;
    if (histA_blocks < 1) histA_blocks = 1;
    k_histA<<<histA_blocks, 256>>>(idx, n_idx, split);

    // histB: half SM capacity so sweepA can co-reside.
    k_histB<<<592, 256>>>(idx, n_idx, split);

    // sweepA: PDL secondary of histB — starts once histB triggers (at entry).
    // No dependency sync needed: it reads only rows < split (finalized by histA).
    int a_threads = split / 4;
    int a_blocks = (a_threads + 255) / 256;
    if (a_blocks < 1) a_blocks = 1;
    {
        cudaLaunchConfig_t cfg = {};
        cfg.gridDim  = dim3((unsigned)a_blocks, 1, 1);
        cfg.blockDim = dim3(256, 1, 1);
        cfg.stream = 0;
        cudaLaunchAttribute attr[1];
        attr[0].id = cudaLaunchAttributeProgrammaticStreamSerialization;
        attr[0].val.programmaticStreamSerializationAllowed = 1;
        cfg.attrs = attr;
        cfg.numAttrs = 1;
        cudaLaunchKernelEx(&cfg, k_sweep, W0, W1, W2, 0, split);
    }

    // sweepB: normal launch -> waits for histB AND sweepA.
    int b_rows = num_emb - split;
    int b_threads = (b_rows + 3) / 4;
    int b_blocks = (b_threads + 255) / 256;
    if (b_blocks < 1) b_blocks = 1;
    k_sweep<<<b_blocks, 256>>>(W0, W1, W2, split, num_emb);

    k_final<<<1, 32>>>((float*)d_out);
}